// round 16
// baseline (speedup 1.0000x reference)
#include <cuda_runtime.h>
#include <cuda_fp16.h>
#include <math.h>
#include <stdint.h>

#define NTT 730
#define NSS 2000
#define NHH 16
#define NRR 15
#define NSH (NSS*NHH)          // 32000
#define NTS (NTT*NSS)          // 1460000

#define L2E2 2.8853900817779268f   // 2*log2(e)
#define W2S 132                    // uint32 row stride: bank = 4r+c (perfect perm)

// -------- scratch (device globals; no allocation) --------
__device__ __align__(128) float    g_b1T[NSS*256];   // [s][k]
__device__ __align__(128) float    g_b2T[NSS*256];
__device__ __align__(128) float4   g_wc4[256];       // first-layer x-coeffs
__device__ __align__(128) uint32_t g_W2h[48*W2S];    // half2 pairs (2p, 2p+1), [o][p]
__device__ __align__(128) float    g_sbias[48];
__device__ __align__(128) float g_k1[NSH], g_k2[NSH], g_k23[NSH], g_k3[NSH];
__device__ __align__(128) float g_gl[NSH], g_qb[NSH], g_ge1[NSH], g_ge2[NSH];
__device__ __align__(128) float g_cw[NSH*NRR];
__device__ __align__(128) float g_vi[(size_t)NTT*NSH];
__device__ __align__(128) float g_vk[(size_t)NTT*NSH];
__device__ __align__(128) float g_vm[(size_t)NTT*NSH];
__device__ __align__(128) float g_Ps[NTS], g_Pl[NTS], g_E[NTS];
__device__ __align__(128) float g_Ssave[4*NSH];      // scan state between chunks
__device__ __align__(128) float g_qwsave[16*NSH];    // conv window between chunks

__device__ __forceinline__ float tanh_fast(float x) {
    float e = __expf(2.f * x);
    return 1.f - __fdividef(2.f, e + 1.f);
}
__device__ __forceinline__ float sigmoid_f(float x) {
    return __fdividef(1.f, 1.f + __expf(-x));
}
__device__ __forceinline__ float hsig(float x) {
    return __saturatef(x * (1.f/6.f) + 0.5f);
}
__device__ __forceinline__ float ex2f(float t) {
    float e; asm("ex2.approx.f32 %0, %1;" : "=f"(e) : "f"(t));
    return e;
}
__device__ __forceinline__ uint32_t packh2(float lo, float hi) {
    __half2 h = __floats2half2_rn(lo, hi);     // x = lo half
    return *reinterpret_cast<uint32_t*>(&h);
}
// pack two fp32 args to half2, tanh both in ONE MUFU op; .lo = first arg
__device__ __forceinline__ uint32_t tanh2(float lo, float hi) {
    uint32_t p;
    asm("cvt.rn.f16x2.f32 %0, %1, %2;" : "=r"(p) : "f"(hi), "f"(lo));
    uint32_t r;
    asm("tanh.approx.f16x2 %0, %1;" : "=r"(r) : "r"(p));
    return r;
}
__device__ __forceinline__ void mma16(float* d, const uint32_t* a,
                                      uint32_t b0, uint32_t b1) {
    asm("mma.sync.aligned.m16n8k16.row.col.f32.f16.f16.f32 "
        "{%0,%1,%2,%3}, {%4,%5,%6,%7}, {%8,%9}, {%0,%1,%2,%3};"
        : "+f"(d[0]), "+f"(d[1]), "+f"(d[2]), "+f"(d[3])
        : "r"(a[0]), "r"(a[1]), "r"(a[2]), "r"(a[3]), "r"(b0), "r"(b1));
}

// =====================================================================
// Kernel A: per-basin MLPs, 8 basins per CTA, W1s staged in SMEM.
// =====================================================================
#define PB 8
#define PREP_SW    0
#define PREP_H     (4*8448)                 // 33792
#define PREP_HR    (PREP_H  + 2048)
#define PREP_W     (PREP_HR + 2048)
#define PREP_WR    (PREP_W  + 1280)
#define PREP_XC    (PREP_WR + 1920)
#define PREP_GA    (PREP_XC + 256)
#define PREP_SMEM_F (PREP_GA + 128)         // 41472 floats
#define PREP_SMEM_BYTES (PREP_SMEM_F*4)     // 165888

__global__ __launch_bounds__(256) void prep_kernel(
    const float* __restrict__ xc,
    const float* __restrict__ fc_W1,  const float* __restrict__ fc_b1,
    const float* __restrict__ fc_W2,  const float* __restrict__ fc_b2,
    const float* __restrict__ fcR_W1, const float* __restrict__ fcR_b1,
    const float* __restrict__ fcR_W2, const float* __restrict__ fcR_b2,
    const float* __restrict__ fcT1_W1,const float* __restrict__ fcT1_b1,
    const float* __restrict__ fcT2_W1,const float* __restrict__ fcT2_b1)
{
    extern __shared__ float psm[];
    float* sW   = psm + PREP_SW;     // 4 matrices, row stride 33
    float* shh  = psm + PREP_H;      // [PB][256]
    float* shhR = psm + PREP_HR;
    float* shw  = psm + PREP_W;      // [PB][160]
    float* shwR = psm + PREP_WR;     // [PB][240]
    float* sxc  = psm + PREP_XC;     // [PB][32]
    float* sga  = psm + PREP_GA;     // [PB][16]

    int s0 = blockIdx.x * PB;
    int tid = threadIdx.x;
    int warp = tid >> 5, lane = tid & 31;

    for (int i = tid; i < 256*32; i += 256) {
        int k = i >> 5, g = i & 31;
        int d = k*33 + g;
        sW[d]           = fc_W1 [i];
        sW[8448 + d]    = fcR_W1[i];
        sW[16896 + d]   = fcT1_W1[k*33 + 1 + g];
        sW[25344 + d]   = fcT2_W1[k*35 + 3 + g];
    }
    for (int i = tid; i < PB*32; i += 256)
        sxc[i] = xc[(s0 + (i >> 5))*32 + (i & 31)];
    __syncthreads();

    {
        int k = tid;
        float bb0 = fc_b1[k], bb1 = fcR_b1[k], bb2 = fcT1_b1[k], bb3 = fcT2_b1[k];
        float a0[PB], a1[PB], a2[PB], a3[PB];
        #pragma unroll
        for (int b = 0; b < PB; b++) { a0[b]=bb0; a1[b]=bb1; a2[b]=bb2; a3[b]=bb3; }
        #pragma unroll 4
        for (int g = 0; g < 32; g++) {
            int d = k*33 + g;
            float w0 = sW[d], w1 = sW[8448+d], w2 = sW[16896+d], w3 = sW[25344+d];
            #pragma unroll
            for (int b = 0; b < PB; b++) {
                float xg = sxc[b*32 + g];
                a0[b] = fmaf(xg, w0, a0[b]);
                a1[b] = fmaf(xg, w1, a1[b]);
                a2[b] = fmaf(xg, w2, a2[b]);
                a3[b] = fmaf(xg, w3, a3[b]);
            }
        }
        #pragma unroll
        for (int b = 0; b < PB; b++) {
            shh [b*256 + k] = tanh_fast(a0[b]);
            shhR[b*256 + k] = tanh_fast(a1[b]);
            g_b1T[(s0+b)*256 + k] = a2[b];
            g_b2T[(s0+b)*256 + k] = a3[b];
        }
    }
    __syncthreads();

    for (int o = warp; o < 400; o += 8) {
        const float* w = (o < 160) ? (fc_W2 + o*256) : (fcR_W2 + (o-160)*256);
        float wreg[8];
        #pragma unroll
        for (int i = 0; i < 8; i++) wreg[i] = w[lane + 32*i];
        float bias = (o < 160) ? fc_b2[o] : fcR_b2[o-160];
        const float* hbase = (o < 160) ? shh : shhR;
        #pragma unroll
        for (int b = 0; b < PB; b++) {
            const float* hh = hbase + b*256;
            float sum = 0.f;
            #pragma unroll
            for (int i = 0; i < 8; i++) sum += hh[lane + 32*i] * wreg[i];
            #pragma unroll
            for (int off = 16; off; off >>= 1)
                sum += __shfl_down_sync(0xffffffffu, sum, off);
            if (lane == 0) {
                if (o < 160) shw [b*160 + o]       = sum + bias;
                else         shwR[b*240 + (o-160)] = sum + bias;
            }
        }
    }
    __syncthreads();

    {
        int b = tid >> 5, hh = tid & 31;
        if (hh < 16) {
            int h = hh, g = (s0 + b)*16 + h;
            const float* swv = shw + b*160;
            g_k1 [g] = sigmoid_f(swv[ 16 + h]);
            g_k2 [g] = sigmoid_f(swv[ 32 + h]);
            g_k23[g] = sigmoid_f(swv[ 48 + h]);
            g_k3 [g] = sigmoid_f(swv[ 64 + h]) * 0.1f;
            g_gl [g] = __expf(swv[ 80 + h]) * 2.f;
            g_qb [g] = fmaxf(swv[112 + h], 0.f);
            g_ge1[g] = fmaxf(swv[128 + h], 0.f);
            g_ge2[g] = fmaxf(swv[144 + h], 0.f);
            float m = -1e30f;
            #pragma unroll
            for (int j = 0; j < 16; j++) m = fmaxf(m, swv[96 + j]);
            float den = 0.f;
            #pragma unroll
            for (int j = 0; j < 16; j++) den += __expf(swv[96 + j] - m);
            sga[b*16 + h] = __fdividef(__expf(swv[96 + h] - m), den);
        }
    }
    __syncthreads();

    for (int i = tid; i < PB*240; i += 256) {
        int b = i / 240, rem = i - b*240;
        int h = rem / 15, d = rem - h*15;
        g_cw[((s0+b)*16 + h)*15 + d] =
            sga[b*16 + h] * fmaxf(shwR[b*240 + h*15 + (14 - d)], 0.f);
    }
}

// =====================================================================
// Kernel A2: pack W2 into half2 (2p, 2p+1) pairs [o][p] + wc/bias tables
// =====================================================================
__global__ __launch_bounds__(256) void pack_kernel(
    const float* __restrict__ fcT1_W1, const float* __restrict__ fcT2_W1,
    const float* __restrict__ fcT1_W2, const float* __restrict__ fcT1_b2,
    const float* __restrict__ fcT2_W2, const float* __restrict__ fcT2_b2)
{
    int tid = threadIdx.x;
    {
        int k = tid;
        g_wc4[k] = make_float4(fcT1_W1[k*33],
                               fcT2_W1[k*35],
                               fcT2_W1[k*35 + 1],
                               fcT2_W1[k*35 + 2]);
    }
    if (tid < 48) g_sbias[tid] = (tid < 32) ? fcT1_b2[tid] : fcT2_b2[tid - 32];

    for (int idx = tid; idx < 48*W2S; idx += 256) {
        int o = idx / W2S, p = idx - o*W2S;
        uint32_t v = 0;
        if (p < 128) {
            int k0 = 2*p, k1 = 2*p + 1;
            float w0 = (o < 32) ? fcT1_W2[o*256 + k0] : fcT2_W2[(o-32)*256 + k0];
            float w1 = (o < 32) ? fcT1_W2[o*256 + k1] : fcT2_W2[(o-32)*256 + k1];
            v = packh2(w0, w1);
        }
        g_W2h[idx] = v;
    }
}

// =====================================================================
// Kernel B: fp16 tensor-core MLP (m16n8k16) + f16x2 tanh.
// warp = 32 timesteps x 1 basin, 2 CTAs/SM. Chunked in t via tile0.
// =====================================================================
#define SMEM_MLP_F (48*W2S + 256*4 + 8*256*2 + 48)   // 11504 floats
#define SMEM_MLP_BYTES (SMEM_MLP_F*4)                // 46016

__global__ __launch_bounds__(256, 2) void mlp_kernel(const float* __restrict__ x,
                                                     int tile0)
{
    extern __shared__ float smem[];
    uint32_t* sW2h  = (uint32_t*)smem;                 // [48*W2S]
    float4*   swc   = (float4*)(smem + 48*W2S);        // [256]
    float2*   sb12  = (float2*)(swc + 256);            // [8][256] {b1,b2}
    float*    sbias = (float*)(sb12 + 8*256);          // [48]

    int tid = threadIdx.x;
    int w = tid >> 5, lane = tid & 31;
    int c = lane & 3, r = lane >> 2;

    {
        const uint4* src = (const uint4*)g_W2h;
        uint4* dst = (uint4*)sW2h;
        for (int i = tid; i < 48*W2S/4; i += 256) dst[i] = src[i];
        swc[tid] = g_wc4[tid];
        if (tid < 48) sbias[tid] = g_sbias[tid];
    }
    int s = blockIdx.y*8 + w;
    {
        const float* b1s = g_b1T + s*256;
        const float* b2s = g_b2T + s*256;
        float2* sb = sb12 + w*256;
        for (int k = lane; k < 256; k += 32)
            sb[k] = make_float2(b1s[k], b2s[k]);
    }
    __syncthreads();

    int t0 = (tile0 + blockIdx.x) * 32;
    int tA = t0 + r;
    int tB = tA + 8;
    int tC = tA + 16;
    int tD = tA + 24;             // may overflow on last tile
    bool vD = (tD < NTT);
    int tDl = vD ? tD : (NTT-1);

    const float* xA = x + (size_t)(tA *NSS + s)*6;
    const float* xB = x + (size_t)(tB *NSS + s)*6;
    const float* xC = x + (size_t)(tC *NSS + s)*6;
    const float* xD = x + (size_t)(tDl*NSS + s)*6;
    float PA = xA[0], EA = xA[1], T1A = xA[2], T2A = xA[3], RA = xA[4], LA = xA[5];
    float PB_ = xB[0], EB = xB[1], T1B = xB[2], T2B = xB[3], RB = xB[4], LB = xB[5];
    float PC = xC[0], EC = xC[1], T1C = xC[2], T2C = xC[3], RC = xC[4], LC = xC[5];
    float PD = xD[0], ED = xD[1], T1D = xD[2], T2D = xD[3], RD = xD[4], LD = xD[5];

    if (c == 0) {
        #pragma unroll
        for (int q = 0; q < 4; q++) {
            float P  = (q==0)?PA :(q==1)?PB_:(q==2)?PC :PD;
            float E  = (q==0)?EA :(q==1)?EB :(q==2)?EC :ED;
            float T1 = (q==0)?T1A:(q==1)?T1B:(q==2)?T1C:T1D;
            float T2 = (q==0)?T2A:(q==1)?T2B:(q==2)?T2C:T2D;
            int   t  = (q==0)?tA :(q==1)?tB :(q==2)?tC :tD;
            if (q == 3 && !vD) break;
            float dn = T2 - T1;
            float rr = (T1 + T2) / (dn == 0.f ? 1.f : dn);
            rr = fminf(fmaxf(rr, -1.f), 1.f);
            if ((T1 >= 0.f) || (T2 <= 0.f)) rr = 0.f;
            float vp = 1.f - acosf(rr) / 3.1415f;
            if (T1 >= 0.f) vp = 1.f;
            if (T2 <= 0.f) vp = 0.f;
            int ts = t*NSS + s;
            g_Ps[ts] = P * (1.f - vp);
            g_Pl[ts] = P * vp;
            g_E[ts]  = E;
        }
    }

    float dAB[6][4], dCD[6][4];
    #pragma unroll
    for (int g = 0; g < 6; g++)
        #pragma unroll
        for (int i = 0; i < 4; i++) { dAB[g][i] = 0.f; dCD[g][i] = 0.f; }

    const float* sbf = (const float*)(sb12 + w*256);

    #define A2F(Rv,T1v,T2v,wc,b) fmaf(Rv, (wc).y, fmaf(T1v, (wc).z, fmaf(T2v, (wc).w, (b))))

    #pragma unroll 1
    for (int j = 0; j < 16; j++) {
        int ka = 16*j + 2*c;        // even
        int kb = ka + 8;
        float4 bA = *(const float4*)(sbf + 2*ka);  // {b1[ka],b2[ka],b1[ka+1],b2[ka+1]}
        float4 bB = *(const float4*)(sbf + 2*kb);
        float4 wA0 = swc[ka], wA1 = swc[ka+1];
        float4 wB0 = swc[kb], wB1 = swc[kb+1];

        uint32_t a1AB[4], a1CD[4], a2AB[4], a2CD[4];
        a1AB[0] = tanh2(fmaf(LA, wA0.x, bA.x), fmaf(LA, wA1.x, bA.z));
        a1AB[1] = tanh2(fmaf(LB, wA0.x, bA.x), fmaf(LB, wA1.x, bA.z));
        a1AB[2] = tanh2(fmaf(LA, wB0.x, bB.x), fmaf(LA, wB1.x, bB.z));
        a1AB[3] = tanh2(fmaf(LB, wB0.x, bB.x), fmaf(LB, wB1.x, bB.z));
        a1CD[0] = tanh2(fmaf(LC, wA0.x, bA.x), fmaf(LC, wA1.x, bA.z));
        a1CD[1] = tanh2(fmaf(LD, wA0.x, bA.x), fmaf(LD, wA1.x, bA.z));
        a1CD[2] = tanh2(fmaf(LC, wB0.x, bB.x), fmaf(LC, wB1.x, bB.z));
        a1CD[3] = tanh2(fmaf(LD, wB0.x, bB.x), fmaf(LD, wB1.x, bB.z));

        a2AB[0] = tanh2(A2F(RA,T1A,T2A,wA0,bA.y), A2F(RA,T1A,T2A,wA1,bA.w));
        a2AB[1] = tanh2(A2F(RB,T1B,T2B,wA0,bA.y), A2F(RB,T1B,T2B,wA1,bA.w));
        a2AB[2] = tanh2(A2F(RA,T1A,T2A,wB0,bB.y), A2F(RA,T1A,T2A,wB1,bB.w));
        a2AB[3] = tanh2(A2F(RB,T1B,T2B,wB0,bB.y), A2F(RB,T1B,T2B,wB1,bB.w));
        a2CD[0] = tanh2(A2F(RC,T1C,T2C,wA0,bA.y), A2F(RC,T1C,T2C,wA1,bA.w));
        a2CD[1] = tanh2(A2F(RD,T1D,T2D,wA0,bA.y), A2F(RD,T1D,T2D,wA1,bA.w));
        a2CD[2] = tanh2(A2F(RC,T1C,T2C,wB0,bB.y), A2F(RC,T1C,T2C,wB1,bB.w));
        a2CD[3] = tanh2(A2F(RD,T1D,T2D,wB0,bB.y), A2F(RD,T1D,T2D,wB1,bB.w));

        const uint32_t* Wb = sW2h + 8*j + c;
        #pragma unroll
        for (int g = 0; g < 4; g++) {
            int ro = (8*g + r)*W2S;
            uint32_t b0 = Wb[ro], b1 = Wb[ro + 4];
            mma16(dAB[g], a1AB, b0, b1);
            mma16(dCD[g], a1CD, b0, b1);
        }
        #pragma unroll
        for (int g = 4; g < 6; g++) {
            int ro = (8*g + r)*W2S;
            uint32_t b0 = Wb[ro], b1 = Wb[ro + 4];
            mma16(dAB[g], a2AB, b0, b1);
            mma16(dCD[g], a2CD, b0, b1);
        }
    }
    #undef A2F

    #pragma unroll
    for (int g = 0; g < 6; g++) {
        int o = 8*g + 2*c;
        float bi0 = sbias[o], bi1 = sbias[o+1];
        float2 oA, oB, oC, oD;
        float* arr;
        if (g < 4) {
            oA = make_float2(hsig(dAB[g][0]+bi0), hsig(dAB[g][1]+bi1));
            oB = make_float2(hsig(dAB[g][2]+bi0), hsig(dAB[g][3]+bi1));
            oC = make_float2(hsig(dCD[g][0]+bi0), hsig(dCD[g][1]+bi1));
            oD = make_float2(hsig(dCD[g][2]+bi0), hsig(dCD[g][3]+bi1));
            arr = (g < 2) ? g_vi : g_vk;
        } else {
            oA = make_float2(ex2f((dAB[g][0]+bi0)*L2E2), ex2f((dAB[g][1]+bi1)*L2E2));
            oB = make_float2(ex2f((dAB[g][2]+bi0)*L2E2), ex2f((dAB[g][3]+bi1)*L2E2));
            oC = make_float2(ex2f((dCD[g][0]+bi0)*L2E2), ex2f((dCD[g][1]+bi1)*L2E2));
            oD = make_float2(ex2f((dCD[g][2]+bi0)*L2E2), ex2f((dCD[g][3]+bi1)*L2E2));
            arr = g_vm;
        }
        int h = o & 15;
        size_t off = (size_t)s*16 + h;
        *(float2*)(arr + (size_t)tA*NSH + off) = oA;
        *(float2*)(arr + (size_t)tB*NSH + off) = oB;
        *(float2*)(arr + (size_t)tC*NSH + off) = oC;
        if (vD) *(float2*)(arr + (size_t)tD*NSH + off) = oD;
    }
}

// =====================================================================
// Kernel C: fused scan + causal conv + head-sum, t-chunked.
// State (S0..S3 + 16-slot Q window) carried between chunks via gmem.
// Chunk boundaries are multiples of 16 so window slots stay aligned.
// =====================================================================
#define SCP 4
__global__ __launch_bounds__(128) void scan_conv_kernel(float* __restrict__ out,
                                                        int t_begin, int t_end,
                                                        int first)
{
    int g = blockIdx.x * 128 + threadIdx.x;     // 250*128 == NSH exactly
    int s = g >> 4;
    float k1 = g_k1[g], k2 = g_k2[g], k23 = g_k23[g], k3 = g_k3[g];
    float gl = g_gl[g], qb = g_qb[g], ge1 = g_ge1[g], ge2 = g_ge2[g];

    float cw[15];
    #pragma unroll
    for (int d = 0; d < 15; d++) cw[d] = g_cw[g*15 + d];

    float S0, Sv, S2, S3;
    float qw[16];
    if (first) {
        S0 = Sv = S2 = S3 = 0.f;
        #pragma unroll
        for (int i = 0; i < 16; i++) qw[i] = 0.f;
    } else {
        S0 = g_Ssave[g];
        Sv = g_Ssave[NSH + g];
        S2 = g_Ssave[2*NSH + g];
        S3 = g_Ssave[3*NSH + g];
        #pragma unroll
        for (int i = 0; i < 16; i++) qw[i] = g_qwsave[i*NSH + g];
    }

    float b_vi[SCP], b_vk[SCP], b_vm[SCP], b_Ps[SCP], b_Pl[SCP], b_E[SCP];
    #pragma unroll
    for (int i = 0; i < SCP; i++) {
        int t = t_begin + i;
        size_t tg = (size_t)t*NSH + g;
        int ts = t*NSS + s;
        b_vi[i] = __ldg(g_vi + tg);
        b_vk[i] = __ldg(g_vk + tg);
        b_vm[i] = __ldg(g_vm + tg);
        b_Ps[i] = __ldg(g_Ps + ts);
        b_Pl[i] = __ldg(g_Pl + ts);
        b_E [i] = __ldg(g_E  + ts);
    }

    for (int tb = t_begin; tb < t_end; tb += 16) {
        #pragma unroll
        for (int u = 0; u < 16; u++) {
            int t = tb + u;
            if (t >= t_end) break;               // uniform across warp
            int slot = u & (SCP-1);

            float Ps = b_Ps[slot], Pl = b_Pl[slot], E = b_E[slot];
            float vi = b_vi[slot], vk = b_vk[slot], vm = b_vm[slot];

            int tn = t + SCP;
            if (tn < NTT) {
                size_t tg = (size_t)tn*NSH + g;
                int ts = tn*NSS + s;
                b_vi[slot] = __ldg(g_vi + tg);
                b_vk[slot] = __ldg(g_vk + tg);
                b_vm[slot] = __ldg(g_vm + tg);
                b_Ps[slot] = __ldg(g_Ps + ts);
                b_Pl[slot] = __ldg(g_Pl + ts);
                b_E [slot] = __ldg(g_E  + ts);
            }

            float H0  = S0 + Ps;
            float qSm = fminf(H0, vm);
            float Hv  = fmaxf(Sv + Pl*(1.f - vi) - E*ge1, 0.f);
            float qv  = Sv * vk;
            float H2  = fmaxf(S2 + qSm + qv - E*ge2 + Pl*vi, 0.f);
            float x1  = H2 - gl;
            float Q1  = (x1 > 0.f) ? exp2f(k1 * __log2f(x1)) : 0.f;
            float q2  = fminf(H2, gl) * k2;
            float Q2  = q2 * (1.f - k23);
            float H3  = S3 + q2 * k23;
            float Q3  = H3 * k3 + qb;

            S0 = H0 - qSm;
            Sv = Hv - qv;
            S2 = H2 - Q1 - q2;
            S3 = H3 - Q3;

            qw[u] = Q1 + Q2 + Q3;                // slot t&15 == u (tb mult of 16)

            float acc = 0.f;
            #pragma unroll
            for (int d = 0; d < 15; d++)
                acc = fmaf(cw[d], qw[(u - d) & 15], acc);

            #pragma unroll
            for (int off = 8; off; off >>= 1)
                acc += __shfl_down_sync(0xffffffffu, acc, off, 16);
            if ((g & 15) == 0)
                out[t*NSS + s] = acc;
        }
    }

    if (t_end < NTT) {
        g_Ssave[g]         = S0;
        g_Ssave[NSH + g]   = Sv;
        g_Ssave[2*NSH + g] = S2;
        g_Ssave[3*NSH + g] = S3;
        #pragma unroll
        for (int i = 0; i < 16; i++) g_qwsave[i*NSH + g] = qw[i];
    }
}

// =====================================================================
extern "C" void kernel_launch(void* const* d_in, const int* in_sizes, int n_in,
                              void* d_out, int out_size)
{
    const float* x       = (const float*)d_in[0];
    const float* xc      = (const float*)d_in[1];
    const float* fc_W1   = (const float*)d_in[2];
    const float* fc_b1   = (const float*)d_in[3];
    const float* fc_W2   = (const float*)d_in[4];
    const float* fc_b2   = (const float*)d_in[5];
    const float* fcR_W1  = (const float*)d_in[6];
    const float* fcR_b1  = (const float*)d_in[7];
    const float* fcR_W2  = (const float*)d_in[8];
    const float* fcR_b2  = (const float*)d_in[9];
    const float* fcT1_W1 = (const float*)d_in[10];
    const float* fcT1_b1 = (const float*)d_in[11];
    const float* fcT1_W2 = (const float*)d_in[12];
    const float* fcT1_b2 = (const float*)d_in[13];
    const float* fcT2_W1 = (const float*)d_in[14];
    const float* fcT2_b1 = (const float*)d_in[15];
    const float* fcT2_W2 = (const float*)d_in[16];
    const float* fcT2_b2 = (const float*)d_in[17];

    // one-time host-side resources (no device memory involved)
    static cudaStream_t sSide = nullptr;
    static cudaEvent_t evFork, evM[4], evJoin;
    if (sSide == nullptr) {
        cudaStreamCreateWithFlags(&sSide, cudaStreamNonBlocking);
        cudaEventCreateWithFlags(&evFork, cudaEventDisableTiming);
        for (int i = 0; i < 4; i++)
            cudaEventCreateWithFlags(&evM[i], cudaEventDisableTiming);
        cudaEventCreateWithFlags(&evJoin, cudaEventDisableTiming);
        cudaFuncSetAttribute(mlp_kernel, cudaFuncAttributeMaxDynamicSharedMemorySize,
                             SMEM_MLP_BYTES);
        cudaFuncSetAttribute(prep_kernel, cudaFuncAttributeMaxDynamicSharedMemorySize,
                             PREP_SMEM_BYTES);
    }

    prep_kernel<<<NSS/PB, 256, PREP_SMEM_BYTES>>>(xc, fc_W1, fc_b1, fc_W2, fc_b2,
                              fcR_W1, fcR_b1, fcR_W2, fcR_b2,
                              fcT1_W1, fcT1_b1, fcT2_W1, fcT2_b1);
    pack_kernel<<<1, 256>>>(fcT1_W1, fcT2_W1, fcT1_W2, fcT1_b2, fcT2_W2, fcT2_b2);

    // fork side stream off the capture stream
    cudaEventRecord(evFork, 0);
    cudaStreamWaitEvent(sSide, evFork, 0);

    // t-tile chunks (32 t per tile): [0,6) [6,12) [12,18) [18,23)
    const int tile0[5] = {0, 6, 12, 18, 23};
    const int tbeg[5]  = {0, 192, 384, 576, NTT};

    for (int k = 0; k < 4; k++) {
        dim3 gB(tile0[k+1] - tile0[k], NSS/8);
        mlp_kernel<<<gB, 256, SMEM_MLP_BYTES>>>(x, tile0[k]);
        cudaEventRecord(evM[k], 0);
        cudaStreamWaitEvent(sSide, evM[k], 0);
        scan_conv_kernel<<<NSH/128, 128, 0, sSide>>>((float*)d_out,
                                                     tbeg[k], tbeg[k+1], k == 0);
    }

    // join back to the capture stream
    cudaEventRecord(evJoin, sSide);
    cudaStreamWaitEvent(0, evJoin, 0);
}

// round 17
// speedup vs baseline: 1.1637x; 1.1637x over previous
#include <cuda_runtime.h>
#include <cuda_fp16.h>
#include <math.h>
#include <stdint.h>

#define NTT 730
#define NSS 2000
#define NHH 16
#define NRR 15
#define NSH (NSS*NHH)          // 32000
#define NTS (NTT*NSS)          // 1460000

#define L2E2 2.8853900817779268f   // 2*log2(e)
#define W2S 132                    // uint32 row stride: bank = 4r+c (perfect perm)

// -------- scratch (device globals; no allocation) --------
__device__ __align__(128) float    g_b1T[NSS*256];   // [s][k]
__device__ __align__(128) float    g_b2T[NSS*256];
__device__ __align__(128) float4   g_wc4[256];       // first-layer x-coeffs
__device__ __align__(128) uint32_t g_W2h[48*W2S];    // half2 pairs (2p, 2p+1), [o][p]
__device__ __align__(128) float    g_sbias[48];
__device__ __align__(128) float g_k1[NSH], g_k2[NSH], g_k23[NSH], g_k3[NSH];
__device__ __align__(128) float g_gl[NSH], g_qb[NSH], g_ge1[NSH], g_ge2[NSH];
__device__ __align__(128) float g_cw[NSH*NRR];
__device__ __align__(128) float g_vi[(size_t)NTT*NSH];
__device__ __align__(128) float g_vk[(size_t)NTT*NSH];
__device__ __align__(128) float g_vm[(size_t)NTT*NSH];
__device__ __align__(128) float g_Ps[NTS], g_Pl[NTS], g_E[NTS];

__device__ __forceinline__ float tanh_fast(float x) {
    float e = __expf(2.f * x);
    return 1.f - __fdividef(2.f, e + 1.f);
}
__device__ __forceinline__ float sigmoid_f(float x) {
    return __fdividef(1.f, 1.f + __expf(-x));
}
__device__ __forceinline__ float hsig(float x) {
    return __saturatef(x * (1.f/6.f) + 0.5f);
}
__device__ __forceinline__ float ex2f(float t) {
    float e; asm("ex2.approx.f32 %0, %1;" : "=f"(e) : "f"(t));
    return e;
}
__device__ __forceinline__ uint32_t packh2(float lo, float hi) {
    __half2 h = __floats2half2_rn(lo, hi);     // x = lo half
    return *reinterpret_cast<uint32_t*>(&h);
}
// pack two fp32 args to half2, tanh both in ONE MUFU op; .lo = first arg
__device__ __forceinline__ uint32_t tanh2(float lo, float hi) {
    uint32_t p;
    asm("cvt.rn.f16x2.f32 %0, %1, %2;" : "=r"(p) : "f"(hi), "f"(lo));
    uint32_t r;
    asm("tanh.approx.f16x2 %0, %1;" : "=r"(r) : "r"(p));
    return r;
}
__device__ __forceinline__ void mma16(float* d, const uint32_t* a,
                                      uint32_t b0, uint32_t b1) {
    asm("mma.sync.aligned.m16n8k16.row.col.f32.f16.f16.f32 "
        "{%0,%1,%2,%3}, {%4,%5,%6,%7}, {%8,%9}, {%0,%1,%2,%3};"
        : "+f"(d[0]), "+f"(d[1]), "+f"(d[2]), "+f"(d[3])
        : "r"(a[0]), "r"(a[1]), "r"(a[2]), "r"(a[3]), "r"(b0), "r"(b1));
}

// =====================================================================
// Kernel A: per-basin MLPs, 8 basins per CTA, W1s staged in SMEM.
// =====================================================================
#define PB 8
#define PREP_SW    0
#define PREP_H     (4*8448)                 // 33792
#define PREP_HR    (PREP_H  + 2048)
#define PREP_W     (PREP_HR + 2048)
#define PREP_WR    (PREP_W  + 1280)
#define PREP_XC    (PREP_WR + 1920)
#define PREP_GA    (PREP_XC + 256)
#define PREP_SMEM_F (PREP_GA + 128)         // 41472 floats
#define PREP_SMEM_BYTES (PREP_SMEM_F*4)     // 165888

__global__ __launch_bounds__(256) void prep_kernel(
    const float* __restrict__ xc,
    const float* __restrict__ fc_W1,  const float* __restrict__ fc_b1,
    const float* __restrict__ fc_W2,  const float* __restrict__ fc_b2,
    const float* __restrict__ fcR_W1, const float* __restrict__ fcR_b1,
    const float* __restrict__ fcR_W2, const float* __restrict__ fcR_b2,
    const float* __restrict__ fcT1_W1,const float* __restrict__ fcT1_b1,
    const float* __restrict__ fcT2_W1,const float* __restrict__ fcT2_b1)
{
    extern __shared__ float psm[];
    float* sW   = psm + PREP_SW;     // 4 matrices, row stride 33
    float* shh  = psm + PREP_H;      // [PB][256]
    float* shhR = psm + PREP_HR;
    float* shw  = psm + PREP_W;      // [PB][160]
    float* shwR = psm + PREP_WR;     // [PB][240]
    float* sxc  = psm + PREP_XC;     // [PB][32]
    float* sga  = psm + PREP_GA;     // [PB][16]

    int s0 = blockIdx.x * PB;
    int tid = threadIdx.x;
    int warp = tid >> 5, lane = tid & 31;

    for (int i = tid; i < 256*32; i += 256) {
        int k = i >> 5, g = i & 31;
        int d = k*33 + g;
        sW[d]           = fc_W1 [i];
        sW[8448 + d]    = fcR_W1[i];
        sW[16896 + d]   = fcT1_W1[k*33 + 1 + g];
        sW[25344 + d]   = fcT2_W1[k*35 + 3 + g];
    }
    for (int i = tid; i < PB*32; i += 256)
        sxc[i] = xc[(s0 + (i >> 5))*32 + (i & 31)];
    __syncthreads();

    {
        int k = tid;
        float bb0 = fc_b1[k], bb1 = fcR_b1[k], bb2 = fcT1_b1[k], bb3 = fcT2_b1[k];
        float a0[PB], a1[PB], a2[PB], a3[PB];
        #pragma unroll
        for (int b = 0; b < PB; b++) { a0[b]=bb0; a1[b]=bb1; a2[b]=bb2; a3[b]=bb3; }
        #pragma unroll 4
        for (int g = 0; g < 32; g++) {
            int d = k*33 + g;
            float w0 = sW[d], w1 = sW[8448+d], w2 = sW[16896+d], w3 = sW[25344+d];
            #pragma unroll
            for (int b = 0; b < PB; b++) {
                float xg = sxc[b*32 + g];
                a0[b] = fmaf(xg, w0, a0[b]);
                a1[b] = fmaf(xg, w1, a1[b]);
                a2[b] = fmaf(xg, w2, a2[b]);
                a3[b] = fmaf(xg, w3, a3[b]);
            }
        }
        #pragma unroll
        for (int b = 0; b < PB; b++) {
            shh [b*256 + k] = tanh_fast(a0[b]);
            shhR[b*256 + k] = tanh_fast(a1[b]);
            g_b1T[(s0+b)*256 + k] = a2[b];
            g_b2T[(s0+b)*256 + k] = a3[b];
        }
    }
    __syncthreads();

    for (int o = warp; o < 400; o += 8) {
        const float* w = (o < 160) ? (fc_W2 + o*256) : (fcR_W2 + (o-160)*256);
        float wreg[8];
        #pragma unroll
        for (int i = 0; i < 8; i++) wreg[i] = w[lane + 32*i];
        float bias = (o < 160) ? fc_b2[o] : fcR_b2[o-160];
        const float* hbase = (o < 160) ? shh : shhR;
        #pragma unroll
        for (int b = 0; b < PB; b++) {
            const float* hh = hbase + b*256;
            float sum = 0.f;
            #pragma unroll
            for (int i = 0; i < 8; i++) sum += hh[lane + 32*i] * wreg[i];
            #pragma unroll
            for (int off = 16; off; off >>= 1)
                sum += __shfl_down_sync(0xffffffffu, sum, off);
            if (lane == 0) {
                if (o < 160) shw [b*160 + o]       = sum + bias;
                else         shwR[b*240 + (o-160)] = sum + bias;
            }
        }
    }
    __syncthreads();

    {
        int b = tid >> 5, hh = tid & 31;
        if (hh < 16) {
            int h = hh, g = (s0 + b)*16 + h;
            const float* swv = shw + b*160;
            g_k1 [g] = sigmoid_f(swv[ 16 + h]);
            g_k2 [g] = sigmoid_f(swv[ 32 + h]);
            g_k23[g] = sigmoid_f(swv[ 48 + h]);
            g_k3 [g] = sigmoid_f(swv[ 64 + h]) * 0.1f;
            g_gl [g] = __expf(swv[ 80 + h]) * 2.f;
            g_qb [g] = fmaxf(swv[112 + h], 0.f);
            g_ge1[g] = fmaxf(swv[128 + h], 0.f);
            g_ge2[g] = fmaxf(swv[144 + h], 0.f);
            float m = -1e30f;
            #pragma unroll
            for (int j = 0; j < 16; j++) m = fmaxf(m, swv[96 + j]);
            float den = 0.f;
            #pragma unroll
            for (int j = 0; j < 16; j++) den += __expf(swv[96 + j] - m);
            sga[b*16 + h] = __fdividef(__expf(swv[96 + h] - m), den);
        }
    }
    __syncthreads();

    for (int i = tid; i < PB*240; i += 256) {
        int b = i / 240, rem = i - b*240;
        int h = rem / 15, d = rem - h*15;
        g_cw[((s0+b)*16 + h)*15 + d] =
            sga[b*16 + h] * fmaxf(shwR[b*240 + h*15 + (14 - d)], 0.f);
    }
}

// =====================================================================
// Kernel A2: pack W2 into half2 (2p, 2p+1) pairs [o][p] + wc/bias tables
// =====================================================================
__global__ __launch_bounds__(256) void pack_kernel(
    const float* __restrict__ fcT1_W1, const float* __restrict__ fcT2_W1,
    const float* __restrict__ fcT1_W2, const float* __restrict__ fcT1_b2,
    const float* __restrict__ fcT2_W2, const float* __restrict__ fcT2_b2)
{
    int tid = threadIdx.x;
    {
        int k = tid;
        g_wc4[k] = make_float4(fcT1_W1[k*33],
                               fcT2_W1[k*35],
                               fcT2_W1[k*35 + 1],
                               fcT2_W1[k*35 + 2]);
    }
    if (tid < 48) g_sbias[tid] = (tid < 32) ? fcT1_b2[tid] : fcT2_b2[tid - 32];

    for (int idx = tid; idx < 48*W2S; idx += 256) {
        int o = idx / W2S, p = idx - o*W2S;
        uint32_t v = 0;
        if (p < 128) {
            int k0 = 2*p, k1 = 2*p + 1;
            float w0 = (o < 32) ? fcT1_W2[o*256 + k0] : fcT2_W2[(o-32)*256 + k0];
            float w1 = (o < 32) ? fcT1_W2[o*256 + k1] : fcT2_W2[(o-32)*256 + k1];
            v = packh2(w0, w1);
        }
        g_W2h[idx] = v;
    }
}

// =====================================================================
// Kernel B: fp16 tensor-core MLP (m16n8k16) + f16x2 tanh.
// warp = 32 timesteps x 1 basin, 2 CTAs/SM. Monolithic (R15 config),
// j-loop unroll 2 for cross-iteration ILP.
// =====================================================================
#define SMEM_MLP_F (48*W2S + 256*4 + 8*256*2 + 48)   // 11504 floats
#define SMEM_MLP_BYTES (SMEM_MLP_F*4)                // 46016

__global__ __launch_bounds__(256, 2) void mlp_kernel(const float* __restrict__ x)
{
    extern __shared__ float smem[];
    uint32_t* sW2h  = (uint32_t*)smem;                 // [48*W2S]
    float4*   swc   = (float4*)(smem + 48*W2S);        // [256]
    float2*   sb12  = (float2*)(swc + 256);            // [8][256] {b1,b2}
    float*    sbias = (float*)(sb12 + 8*256);          // [48]

    int tid = threadIdx.x;
    int w = tid >> 5, lane = tid & 31;
    int c = lane & 3, r = lane >> 2;

    {
        const uint4* src = (const uint4*)g_W2h;
        uint4* dst = (uint4*)sW2h;
        for (int i = tid; i < 48*W2S/4; i += 256) dst[i] = src[i];
        swc[tid] = g_wc4[tid];
        if (tid < 48) sbias[tid] = g_sbias[tid];
    }
    int s = blockIdx.y*8 + w;
    {
        const float* b1s = g_b1T + s*256;
        const float* b2s = g_b2T + s*256;
        float2* sb = sb12 + w*256;
        for (int k = lane; k < 256; k += 32)
            sb[k] = make_float2(b1s[k], b2s[k]);
    }
    __syncthreads();

    int t0 = blockIdx.x * 32;
    int tA = t0 + r;
    int tB = tA + 8;
    int tC = tA + 16;
    int tD = tA + 24;             // may overflow on last tile
    bool vD = (tD < NTT);
    int tDl = vD ? tD : (NTT-1);

    const float* xA = x + (size_t)(tA *NSS + s)*6;
    const float* xB = x + (size_t)(tB *NSS + s)*6;
    const float* xC = x + (size_t)(tC *NSS + s)*6;
    const float* xD = x + (size_t)(tDl*NSS + s)*6;
    float PA = xA[0], EA = xA[1], T1A = xA[2], T2A = xA[3], RA = xA[4], LA = xA[5];
    float PB_ = xB[0], EB = xB[1], T1B = xB[2], T2B = xB[3], RB = xB[4], LB = xB[5];
    float PC = xC[0], EC = xC[1], T1C = xC[2], T2C = xC[3], RC = xC[4], LC = xC[5];
    float PD = xD[0], ED = xD[1], T1D = xD[2], T2D = xD[3], RD = xD[4], LD = xD[5];

    if (c == 0) {
        #pragma unroll
        for (int q = 0; q < 4; q++) {
            float P  = (q==0)?PA :(q==1)?PB_:(q==2)?PC :PD;
            float E  = (q==0)?EA :(q==1)?EB :(q==2)?EC :ED;
            float T1 = (q==0)?T1A:(q==1)?T1B:(q==2)?T1C:T1D;
            float T2 = (q==0)?T2A:(q==1)?T2B:(q==2)?T2C:T2D;
            int   t  = (q==0)?tA :(q==1)?tB :(q==2)?tC :tD;
            if (q == 3 && !vD) break;
            float dn = T2 - T1;
            float rr = (T1 + T2) / (dn == 0.f ? 1.f : dn);
            rr = fminf(fmaxf(rr, -1.f), 1.f);
            if ((T1 >= 0.f) || (T2 <= 0.f)) rr = 0.f;
            float vp = 1.f - acosf(rr) / 3.1415f;
            if (T1 >= 0.f) vp = 1.f;
            if (T2 <= 0.f) vp = 0.f;
            int ts = t*NSS + s;
            g_Ps[ts] = P * (1.f - vp);
            g_Pl[ts] = P * vp;
            g_E[ts]  = E;
        }
    }

    float dAB[6][4], dCD[6][4];
    #pragma unroll
    for (int g = 0; g < 6; g++)
        #pragma unroll
        for (int i = 0; i < 4; i++) { dAB[g][i] = 0.f; dCD[g][i] = 0.f; }

    const float* sbf = (const float*)(sb12 + w*256);

    #define A2F(Rv,T1v,T2v,wc,b) fmaf(Rv, (wc).y, fmaf(T1v, (wc).z, fmaf(T2v, (wc).w, (b))))

    #pragma unroll 2
    for (int j = 0; j < 16; j++) {
        int ka = 16*j + 2*c;        // even
        int kb = ka + 8;
        float4 bA = *(const float4*)(sbf + 2*ka);  // {b1[ka],b2[ka],b1[ka+1],b2[ka+1]}
        float4 bB = *(const float4*)(sbf + 2*kb);
        float4 wA0 = swc[ka], wA1 = swc[ka+1];
        float4 wB0 = swc[kb], wB1 = swc[kb+1];

        uint32_t a1AB[4], a1CD[4], a2AB[4], a2CD[4];
        a1AB[0] = tanh2(fmaf(LA, wA0.x, bA.x), fmaf(LA, wA1.x, bA.z));
        a1AB[1] = tanh2(fmaf(LB, wA0.x, bA.x), fmaf(LB, wA1.x, bA.z));
        a1AB[2] = tanh2(fmaf(LA, wB0.x, bB.x), fmaf(LA, wB1.x, bB.z));
        a1AB[3] = tanh2(fmaf(LB, wB0.x, bB.x), fmaf(LB, wB1.x, bB.z));
        a1CD[0] = tanh2(fmaf(LC, wA0.x, bA.x), fmaf(LC, wA1.x, bA.z));
        a1CD[1] = tanh2(fmaf(LD, wA0.x, bA.x), fmaf(LD, wA1.x, bA.z));
        a1CD[2] = tanh2(fmaf(LC, wB0.x, bB.x), fmaf(LC, wB1.x, bB.z));
        a1CD[3] = tanh2(fmaf(LD, wB0.x, bB.x), fmaf(LD, wB1.x, bB.z));

        a2AB[0] = tanh2(A2F(RA,T1A,T2A,wA0,bA.y), A2F(RA,T1A,T2A,wA1,bA.w));
        a2AB[1] = tanh2(A2F(RB,T1B,T2B,wA0,bA.y), A2F(RB,T1B,T2B,wA1,bA.w));
        a2AB[2] = tanh2(A2F(RA,T1A,T2A,wB0,bB.y), A2F(RA,T1A,T2A,wB1,bB.w));
        a2AB[3] = tanh2(A2F(RB,T1B,T2B,wB0,bB.y), A2F(RB,T1B,T2B,wB1,bB.w));
        a2CD[0] = tanh2(A2F(RC,T1C,T2C,wA0,bA.y), A2F(RC,T1C,T2C,wA1,bA.w));
        a2CD[1] = tanh2(A2F(RD,T1D,T2D,wA0,bA.y), A2F(RD,T1D,T2D,wA1,bA.w));
        a2CD[2] = tanh2(A2F(RC,T1C,T2C,wB0,bB.y), A2F(RC,T1C,T2C,wB1,bB.w));
        a2CD[3] = tanh2(A2F(RD,T1D,T2D,wB0,bB.y), A2F(RD,T1D,T2D,wB1,bB.w));

        const uint32_t* Wb = sW2h + 8*j + c;
        #pragma unroll
        for (int g = 0; g < 4; g++) {
            int ro = (8*g + r)*W2S;
            uint32_t b0 = Wb[ro], b1 = Wb[ro + 4];
            mma16(dAB[g], a1AB, b0, b1);
            mma16(dCD[g], a1CD, b0, b1);
        }
        #pragma unroll
        for (int g = 4; g < 6; g++) {
            int ro = (8*g + r)*W2S;
            uint32_t b0 = Wb[ro], b1 = Wb[ro + 4];
            mma16(dAB[g], a2AB, b0, b1);
            mma16(dCD[g], a2CD, b0, b1);
        }
    }
    #undef A2F

    #pragma unroll
    for (int g = 0; g < 6; g++) {
        int o = 8*g + 2*c;
        float bi0 = sbias[o], bi1 = sbias[o+1];
        float2 oA, oB, oC, oD;
        float* arr;
        if (g < 4) {
            oA = make_float2(hsig(dAB[g][0]+bi0), hsig(dAB[g][1]+bi1));
            oB = make_float2(hsig(dAB[g][2]+bi0), hsig(dAB[g][3]+bi1));
            oC = make_float2(hsig(dCD[g][0]+bi0), hsig(dCD[g][1]+bi1));
            oD = make_float2(hsig(dCD[g][2]+bi0), hsig(dCD[g][3]+bi1));
            arr = (g < 2) ? g_vi : g_vk;
        } else {
            oA = make_float2(ex2f((dAB[g][0]+bi0)*L2E2), ex2f((dAB[g][1]+bi1)*L2E2));
            oB = make_float2(ex2f((dAB[g][2]+bi0)*L2E2), ex2f((dAB[g][3]+bi1)*L2E2));
            oC = make_float2(ex2f((dCD[g][0]+bi0)*L2E2), ex2f((dCD[g][1]+bi1)*L2E2));
            oD = make_float2(ex2f((dCD[g][2]+bi0)*L2E2), ex2f((dCD[g][3]+bi1)*L2E2));
            arr = g_vm;
        }
        int h = o & 15;
        size_t off = (size_t)s*16 + h;
        *(float2*)(arr + (size_t)tA*NSH + off) = oA;
        *(float2*)(arr + (size_t)tB*NSH + off) = oB;
        *(float2*)(arr + (size_t)tC*NSH + off) = oC;
        if (vD) *(float2*)(arr + (size_t)tD*NSH + off) = oD;
    }
}

// =====================================================================
// Kernel C: fused scan + causal conv + head-sum (R15 measured-best).
// thread = (s,h); 16-slot register Q window (static slots); per-t
// 15-tap conv + width-16 shfl reduction; lane h==0 writes out[t,s].
// =====================================================================
#define SCP 4
__global__ __launch_bounds__(128) void scan_conv_kernel(float* __restrict__ out)
{
    int g = blockIdx.x * 128 + threadIdx.x;     // 250*128 == NSH exactly
    int s = g >> 4;
    float k1 = g_k1[g], k2 = g_k2[g], k23 = g_k23[g], k3 = g_k3[g];
    float gl = g_gl[g], qb = g_qb[g], ge1 = g_ge1[g], ge2 = g_ge2[g];
    float S0 = 0.f, Sv = 0.f, S2 = 0.f, S3 = 0.f;

    float cw[15];
    #pragma unroll
    for (int d = 0; d < 15; d++) cw[d] = g_cw[g*15 + d];

    float qw[16];
    #pragma unroll
    for (int i = 0; i < 16; i++) qw[i] = 0.f;

    float b_vi[SCP], b_vk[SCP], b_vm[SCP], b_Ps[SCP], b_Pl[SCP], b_E[SCP];
    #pragma unroll
    for (int i = 0; i < SCP; i++) {
        size_t tg = (size_t)i*NSH + g;
        int ts = i*NSS + s;
        b_vi[i] = __ldg(g_vi + tg);
        b_vk[i] = __ldg(g_vk + tg);
        b_vm[i] = __ldg(g_vm + tg);
        b_Ps[i] = __ldg(g_Ps + ts);
        b_Pl[i] = __ldg(g_Pl + ts);
        b_E [i] = __ldg(g_E  + ts);
    }

    for (int tb = 0; tb < NTT; tb += 16) {
        #pragma unroll
        for (int u = 0; u < 16; u++) {
            int t = tb + u;
            if (t >= NTT) break;                 // uniform across warp
            int slot = u & (SCP-1);

            float Ps = b_Ps[slot], Pl = b_Pl[slot], E = b_E[slot];
            float vi = b_vi[slot], vk = b_vk[slot], vm = b_vm[slot];

            int tn = t + SCP;
            if (tn < NTT) {
                size_t tg = (size_t)tn*NSH + g;
                int ts = tn*NSS + s;
                b_vi[slot] = __ldg(g_vi + tg);
                b_vk[slot] = __ldg(g_vk + tg);
                b_vm[slot] = __ldg(g_vm + tg);
                b_Ps[slot] = __ldg(g_Ps + ts);
                b_Pl[slot] = __ldg(g_Pl + ts);
                b_E [slot] = __ldg(g_E  + ts);
            }

            float H0  = S0 + Ps;
            float qSm = fminf(H0, vm);
            float Hv  = fmaxf(Sv + Pl*(1.f - vi) - E*ge1, 0.f);
            float qv  = Sv * vk;
            float H2  = fmaxf(S2 + qSm + qv - E*ge2 + Pl*vi, 0.f);
            float x1  = H2 - gl;
            float Q1  = (x1 > 0.f) ? exp2f(k1 * __log2f(x1)) : 0.f;
            float q2  = fminf(H2, gl) * k2;
            float Q2  = q2 * (1.f - k23);
            float H3  = S3 + q2 * k23;
            float Q3  = H3 * k3 + qb;

            S0 = H0 - qSm;
            Sv = Hv - qv;
            S2 = H2 - Q1 - q2;
            S3 = H3 - Q3;

            qw[u] = Q1 + Q2 + Q3;                // slot t&15 == u (static)

            float acc = 0.f;
            #pragma unroll
            for (int d = 0; d < 15; d++)
                acc = fmaf(cw[d], qw[(u - d) & 15], acc);

            #pragma unroll
            for (int off = 8; off; off >>= 1)
                acc += __shfl_down_sync(0xffffffffu, acc, off, 16);
            if ((g & 15) == 0)
                out[t*NSS + s] = acc;
        }
    }
}

// =====================================================================
extern "C" void kernel_launch(void* const* d_in, const int* in_sizes, int n_in,
                              void* d_out, int out_size)
{
    const float* x       = (const float*)d_in[0];
    const float* xc      = (const float*)d_in[1];
    const float* fc_W1   = (const float*)d_in[2];
    const float* fc_b1   = (const float*)d_in[3];
    const float* fc_W2   = (const float*)d_in[4];
    const float* fc_b2   = (const float*)d_in[5];
    const float* fcR_W1  = (const float*)d_in[6];
    const float* fcR_b1  = (const float*)d_in[7];
    const float* fcR_W2  = (const float*)d_in[8];
    const float* fcR_b2  = (const float*)d_in[9];
    const float* fcT1_W1 = (const float*)d_in[10];
    const float* fcT1_b1 = (const float*)d_in[11];
    const float* fcT1_W2 = (const float*)d_in[12];
    const float* fcT1_b2 = (const float*)d_in[13];
    const float* fcT2_W1 = (const float*)d_in[14];
    const float* fcT2_b1 = (const float*)d_in[15];
    const float* fcT2_W2 = (const float*)d_in[16];
    const float* fcT2_b2 = (const float*)d_in[17];

    cudaFuncSetAttribute(mlp_kernel, cudaFuncAttributeMaxDynamicSharedMemorySize,
                         SMEM_MLP_BYTES);
    cudaFuncSetAttribute(prep_kernel, cudaFuncAttributeMaxDynamicSharedMemorySize,
                         PREP_SMEM_BYTES);

    prep_kernel<<<NSS/PB, 256, PREP_SMEM_BYTES>>>(xc, fc_W1, fc_b1, fc_W2, fc_b2,
                              fcR_W1, fcR_b1, fcR_W2, fcR_b2,
                              fcT1_W1, fcT1_b1, fcT2_W1, fcT2_b1);

    pack_kernel<<<1, 256>>>(fcT1_W1, fcT2_W1, fcT1_W2, fcT1_b2, fcT2_W2, fcT2_b2);

    dim3 gB((NTT + 31)/32, NSS/8);
    mlp_kernel<<<gB, 256, SMEM_MLP_BYTES>>>(x);

    scan_conv_kernel<<<NSH/128, 128>>>((float*)d_out);
}